// round 7
// baseline (speedup 1.0000x reference)
#include <cuda_runtime.h>

#define N_NODES 50000
#define N_EDGES 600000
#define D 128
#define CAP 64            // per-node neighbor bucket capacity (Poisson λ=12)
#define BN_EPS 1e-5f

// Scratch (allocation-free rule: __device__ globals)
__device__ __align__(16) float g_h [N_NODES * D];   // x + aggregated neighbors
__device__ __align__(16) float g_h1[N_NODES * D];   // relu(h @ W1 + b1)
__device__ int   g_cnt [N_NODES];                   // in-degree counters
__device__ int   g_srcs[N_NODES * CAP];             // bucketed src lists
__device__ float g_sum[D];
__device__ float g_sq [D];
__device__ __align__(16) float g_W2l [D * 2];       // W2 @ Wl
__device__ __align__(16) float g_Weff[D * 2];
__device__ float g_ceff[2];

// ---------------------------------------------------------------------------
// Kernel 1 (k_pre): zero counters + stat accumulators, AND compute
// W2l = W2 @ Wl in the same launch (disjoint block ranges).
//   blocks [0, NB_CNT)   : zero g_cnt
//   blocks [NB_CNT, +16) : W2l, one warp per output row f (8 warps/block)
//   block  NB_CNT+16     : zero g_sum/g_sq
// ---------------------------------------------------------------------------
#define NB_CNT ((N_NODES + 255) / 256)
__global__ void k_pre(const float* __restrict__ W2, const float* __restrict__ Wl) {
    int b = blockIdx.x;
    if (b < NB_CNT) {
        int i = b * 256 + threadIdx.x;
        if (i < N_NODES) g_cnt[i] = 0;
        return;
    }
    if (b < NB_CNT + 16) {
        int f    = (b - NB_CNT) * 8 + (threadIdx.x >> 5);
        int lane = threadIdx.x & 31;
        float4 a  = __ldg((const float4*)(W2 + f * D) + lane);
        float4 w0 = __ldg((const float4*)Wl + lane * 2 + 0); // k0c0 k0c1 k1c0 k1c1
        float4 w1 = __ldg((const float4*)Wl + lane * 2 + 1); // k2c0 k2c1 k3c0 k3c1
        float s0 = a.x * w0.x + a.y * w0.z + a.z * w1.x + a.w * w1.z;
        float s1 = a.x * w0.y + a.y * w0.w + a.z * w1.y + a.w * w1.w;
        #pragma unroll
        for (int o = 16; o > 0; o >>= 1) {
            s0 += __shfl_down_sync(0xFFFFFFFFu, s0, o);
            s1 += __shfl_down_sync(0xFFFFFFFFu, s1, o);
        }
        if (lane == 0) {
            g_W2l[f * 2 + 0] = s0;
            g_W2l[f * 2 + 1] = s1;
        }
        return;
    }
    if (threadIdx.x < D) {
        g_sum[threadIdx.x] = 0.f;
        g_sq [threadIdx.x] = 0.f;
    }
}

// ---------------------------------------------------------------------------
// Kernel 2 (k_place): bucket edges by dst. One thread per edge (int32 index).
// No g_h writes at all; overflow (deg > CAP) only bumps the counter —
// the rare-path scan in k_agg handles it.
// ---------------------------------------------------------------------------
__global__ void k_place(const int* __restrict__ ei) {
    int e = blockIdx.x * blockDim.x + threadIdx.x;
    if (e >= N_EDGES) return;
    int src = __ldg(&ei[e]);
    int dst = __ldg(&ei[N_EDGES + e]);
    if (((unsigned)src >= N_NODES) | ((unsigned)dst >= N_NODES)) return;
    int pos = atomicAdd(&g_cnt[dst], 1);
    if (pos < CAP) g_srcs[dst * CAP + pos] = src;
}

// ---------------------------------------------------------------------------
// Kernel 3 (k_agg): h[n] = x[n] + sum of neighbor rows. One warp per node;
// the ONLY writer of g_h (init copy eliminated). Overflow belt: if deg > CAP
// (P ~ 1e-30), the warp rescans the full edge list for dst==n.
// ---------------------------------------------------------------------------
__global__ void k_agg(const float* __restrict__ x, const int* __restrict__ ei) {
    int n    = (blockIdx.x * blockDim.x + threadIdx.x) >> 5;
    int lane = threadIdx.x & 31;
    if (n >= N_NODES) return;
    int cnt = g_cnt[n];
    float4 acc = __ldg((const float4*)(x + (size_t)n * D) + lane);

    if (cnt <= CAP) {
        const int* s = g_srcs + n * CAP;
        int j = 0;
        for (; j + 2 <= cnt; j += 2) {            // 2-deep pipeline
            int s0 = __ldg(&s[j]);
            int s1 = __ldg(&s[j + 1]);
            float4 v0 = __ldg((const float4*)(x + (size_t)s0 * D) + lane);
            float4 v1 = __ldg((const float4*)(x + (size_t)s1 * D) + lane);
            acc.x += v0.x + v1.x; acc.y += v0.y + v1.y;
            acc.z += v0.z + v1.z; acc.w += v0.w + v1.w;
        }
        if (j < cnt) {
            int s0 = __ldg(&s[j]);
            float4 v0 = __ldg((const float4*)(x + (size_t)s0 * D) + lane);
            acc.x += v0.x; acc.y += v0.y; acc.z += v0.z; acc.w += v0.w;
        }
    } else {
        // rare path: full scan (correctness belt; never executes for λ=12)
        for (int e = 0; e < N_EDGES; e++) {
            if (__ldg(&ei[N_EDGES + e]) == n) {
                int s0 = __ldg(&ei[e]);
                if ((unsigned)s0 < N_NODES) {
                    float4 v0 = __ldg((const float4*)(x + (size_t)s0 * D) + lane);
                    acc.x += v0.x; acc.y += v0.y; acc.z += v0.z; acc.w += v0.w;
                }
            }
        }
    }
    *(float4*)(g_h + (size_t)n * D + lane * 4) = acc;
}

// ---------------------------------------------------------------------------
// Kernel 4: h1 = relu(h @ W1 + b1), fused per-feature sum / sumsq partials.
// Tile: 64 rows x 128 cols per block, 256 threads, 8x4 outputs per thread.
// Inner loop uses explicit LDS.128 for the B fragment.
// ---------------------------------------------------------------------------
__global__ void k_gemm1(const float* __restrict__ W1,
                        const float* __restrict__ b1) {
    __shared__ float As[32][65];      // (k+m)%32 banks: conflict-free stores
    __shared__ __align__(16) float Bs[32][128];
    __shared__ float s_sum[128];
    __shared__ float s_sq [128];

    int t  = threadIdx.x;
    int tx = t & 31;                  // N-group: cols tx*4 .. tx*4+3
    int ty = t >> 5;                  // M-group: rows ty*8 .. ty*8+7
    int rowBase = blockIdx.x * 64;

    float acc[8][4];
    #pragma unroll
    for (int i = 0; i < 8; i++)
        #pragma unroll
        for (int j = 0; j < 4; j++) acc[i][j] = 0.f;

    for (int kc = 0; kc < D; kc += 32) {
        #pragma unroll
        for (int i = 0; i < 8; i++) {
            int idx = t + i * 256;            // 0..2047
            int k = idx & 31, m = idx >> 5;
            int row = rowBase + m;
            As[k][m] = (row < N_NODES) ? g_h[row * D + kc + k] : 0.f;
        }
        #pragma unroll
        for (int i = 0; i < 16; i++) {
            int idx = t + i * 256;            // 0..4095
            int n = idx & 127, k = idx >> 7;
            Bs[k][n] = W1[(kc + k) * D + n];
        }
        __syncthreads();

        #pragma unroll
        for (int k = 0; k < 32; k++) {
            float4 bv = *(const float4*)&Bs[k][tx * 4];   // LDS.128
            #pragma unroll
            for (int i = 0; i < 8; i++) {
                float a = As[k][ty * 8 + i];              // warp-broadcast
                acc[i][0] += a * bv.x;
                acc[i][1] += a * bv.y;
                acc[i][2] += a * bv.z;
                acc[i][3] += a * bv.w;
            }
        }
        __syncthreads();
    }

    if (t < 128) { s_sum[t] = 0.f; s_sq[t] = 0.f; }
    __syncthreads();

    float4 bb = *(const float4*)(b1 + tx * 4);
    float psum[4] = {0.f, 0.f, 0.f, 0.f};
    float psq [4] = {0.f, 0.f, 0.f, 0.f};

    #pragma unroll
    for (int i = 0; i < 8; i++) {
        int row = rowBase + ty * 8 + i;
        if (row < N_NODES) {
            float4 hv;
            hv.x = fmaxf(acc[i][0] + bb.x, 0.f);
            hv.y = fmaxf(acc[i][1] + bb.y, 0.f);
            hv.z = fmaxf(acc[i][2] + bb.z, 0.f);
            hv.w = fmaxf(acc[i][3] + bb.w, 0.f);
            *(float4*)(g_h1 + (size_t)row * D + tx * 4) = hv;
            psum[0] += hv.x; psq[0] += hv.x * hv.x;
            psum[1] += hv.y; psq[1] += hv.y * hv.y;
            psum[2] += hv.z; psq[2] += hv.z * hv.z;
            psum[3] += hv.w; psq[3] += hv.w * hv.w;
        }
    }
    #pragma unroll
    for (int j = 0; j < 4; j++) {
        atomicAdd(&s_sum[tx * 4 + j], psum[j]);
        atomicAdd(&s_sq [tx * 4 + j], psq [j]);
    }
    __syncthreads();
    if (t < 128) {
        atomicAdd(&g_sum[t], s_sum[t]);
        atomicAdd(&g_sq [t], s_sq [t]);
    }
}

// ---------------------------------------------------------------------------
// Kernel 5 (1 block, 128 threads): finalize BN stats, fold into Weff/ceff.
//   g_f     = rsqrt(var_f + eps) * gamma_f
//   Weff    = g_f * W2l[f,c]
//   ceff[c] = bl[c] + sum_f [ (beta_f - mean_f*g_f)*W2l[f,c] + b2[f]*Wl[f,c] ]
// ---------------------------------------------------------------------------
__global__ void k_stats(const float* __restrict__ b2, const float* __restrict__ Wl,
                        const float* __restrict__ bl,
                        const float* __restrict__ gamma, const float* __restrict__ beta) {
    int f = threadIdx.x;   // 0..127
    float mean = g_sum[f] * (1.0f / N_NODES);
    float var  = g_sq [f] * (1.0f / N_NODES) - mean * mean;
    float g    = rsqrtf(var + BN_EPS) * gamma[f];

    float w2l0 = g_W2l[f * 2 + 0];
    float w2l1 = g_W2l[f * 2 + 1];
    g_Weff[f * 2 + 0] = g * w2l0;
    g_Weff[f * 2 + 1] = g * w2l1;

    float bias = beta[f] - mean * g;
    float p0 = bias * w2l0 + b2[f] * Wl[f * 2 + 0];
    float p1 = bias * w2l1 + b2[f] * Wl[f * 2 + 1];

    __shared__ float r0[128], r1[128];
    r0[f] = p0; r1[f] = p1;
    __syncthreads();
    for (int s = 64; s > 0; s >>= 1) {
        if (f < s) { r0[f] += r0[f + s]; r1[f] += r1[f + s]; }
        __syncthreads();
    }
    if (f == 0) {
        g_ceff[0] = r0[0] + bl[0];
        g_ceff[1] = r1[0] + bl[1];
    }
}

// ---------------------------------------------------------------------------
// Kernel 6: out[n,c] = dot(h1[n,:], Weff[:,c]) + ceff[c]. One warp per node.
// ---------------------------------------------------------------------------
__global__ void k_out(float* __restrict__ out) {
    __shared__ float w[256];
    __shared__ float c0s, c1s;
    int t = threadIdx.x;
    w[t] = g_Weff[t];
    if (t == 0) { c0s = g_ceff[0]; c1s = g_ceff[1]; }
    __syncthreads();

    int lane = t & 31;
    int n = (blockIdx.x * blockDim.x + t) >> 5;     // one node per warp
    if (n >= N_NODES) return;

    float4 h = *(const float4*)(g_h1 + (size_t)n * D + lane * 4);
    int b = lane * 8;  // f = lane*4+q -> w[(lane*4+q)*2 + c]
    float s0 = h.x * w[b + 0] + h.y * w[b + 2] + h.z * w[b + 4] + h.w * w[b + 6];
    float s1 = h.x * w[b + 1] + h.y * w[b + 3] + h.z * w[b + 5] + h.w * w[b + 7];
    #pragma unroll
    for (int o = 16; o > 0; o >>= 1) {
        s0 += __shfl_down_sync(0xFFFFFFFFu, s0, o);
        s1 += __shfl_down_sync(0xFFFFFFFFu, s1, o);
    }
    if (lane == 0) {
        out[n * 2 + 0] = s0 + c0s;
        out[n * 2 + 1] = s1 + c1s;
    }
}

// ---------------------------------------------------------------------------
extern "C" void kernel_launch(void* const* d_in, const int* in_sizes, int n_in,
                              void* d_out, int out_size) {
    const float* x     = (const float*)d_in[0];
    const int*   ei    = (const int*)  d_in[1];   // int32 (JAX x64-disabled)
    const float* W1    = (const float*)d_in[2];
    const float* b1    = (const float*)d_in[3];
    const float* gamma = (const float*)d_in[4];
    const float* beta  = (const float*)d_in[5];
    const float* W2    = (const float*)d_in[6];
    const float* b2    = (const float*)d_in[7];
    const float* Wl    = (const float*)d_in[8];
    const float* bl    = (const float*)d_in[9];
    float*       out   = (float*)      d_out;

    // 1) zero counters/stats + W2l = W2@Wl (one merged launch)
    k_pre<<<NB_CNT + 17, 256>>>(W2, Wl);
    // 2) bucket edges by dst (one thread per edge)
    k_place<<<(N_EDGES + 255) / 256, 256>>>(ei);
    // 3) h = x + aggregate (one warp per node; sole writer of g_h)
    k_agg<<<(N_NODES * 32 + 255) / 256, 256>>>(x, ei);
    // 4) h1 = relu(h@W1+b1) + BN stat partials
    k_gemm1<<<(N_NODES + 63) / 64, 256>>>(W1, b1);
    // 5) finalize BN + fold into Weff[128x2], ceff[2]
    k_stats<<<1, 128>>>(b2, Wl, bl, gamma, beta);
    // 6) out = h1 @ Weff + ceff
    k_out<<<(N_NODES * 32 + 255) / 256, 256>>>(out);
}

// round 8
// speedup vs baseline: 1.0185x; 1.0185x over previous
#include <cuda_runtime.h>

#define N_NODES 50000
#define N_EDGES 600000
#define D 128
#define CAP 64            // per-node neighbor bucket capacity (Poisson λ=12)
#define BN_EPS 1e-5f

// Scratch (allocation-free rule: __device__ globals)
__device__ __align__(16) float g_h [N_NODES * D];   // x + aggregated neighbors
__device__ __align__(16) float g_h1[N_NODES * D];   // relu(h @ W1 + b1)
__device__ int   g_cnt [N_NODES];                   // in-degree counters
__device__ int   g_srcs[N_NODES * CAP];             // bucketed src lists
__device__ float g_sum[D];
__device__ float g_sq [D];
__device__ __align__(16) float g_W2l [D * 2];       // W2 @ Wl
__device__ __align__(16) float g_Weff[D * 2];
__device__ float g_ceff[2];

// ---------------------------------------------------------------------------
// Kernel 1 (k_pre): zero counters + stat accumulators, AND compute
// W2l = W2 @ Wl in the same launch (disjoint block ranges).
//   blocks [0, NB_CNT)   : zero g_cnt
//   blocks [NB_CNT, +16) : W2l, one warp per output row f (8 warps/block)
//   block  NB_CNT+16     : zero g_sum/g_sq
// ---------------------------------------------------------------------------
#define NB_CNT ((N_NODES + 255) / 256)
__global__ void k_pre(const float* __restrict__ W2, const float* __restrict__ Wl) {
    int b = blockIdx.x;
    if (b < NB_CNT) {
        int i = b * 256 + threadIdx.x;
        if (i < N_NODES) g_cnt[i] = 0;
        return;
    }
    if (b < NB_CNT + 16) {
        int f    = (b - NB_CNT) * 8 + (threadIdx.x >> 5);
        int lane = threadIdx.x & 31;
        float4 a  = __ldg((const float4*)(W2 + f * D) + lane);
        float4 w0 = __ldg((const float4*)Wl + lane * 2 + 0); // k0c0 k0c1 k1c0 k1c1
        float4 w1 = __ldg((const float4*)Wl + lane * 2 + 1); // k2c0 k2c1 k3c0 k3c1
        float s0 = a.x * w0.x + a.y * w0.z + a.z * w1.x + a.w * w1.z;
        float s1 = a.x * w0.y + a.y * w0.w + a.z * w1.y + a.w * w1.w;
        #pragma unroll
        for (int o = 16; o > 0; o >>= 1) {
            s0 += __shfl_down_sync(0xFFFFFFFFu, s0, o);
            s1 += __shfl_down_sync(0xFFFFFFFFu, s1, o);
        }
        if (lane == 0) {
            g_W2l[f * 2 + 0] = s0;
            g_W2l[f * 2 + 1] = s1;
        }
        return;
    }
    if (threadIdx.x < D) {
        g_sum[threadIdx.x] = 0.f;
        g_sq [threadIdx.x] = 0.f;
    }
}

// ---------------------------------------------------------------------------
// Kernel 2 (k_place): bucket edges by dst. One thread per edge (int32 index).
// No g_h writes at all; overflow (deg > CAP) only bumps the counter —
// the rare-path scan in k_agg handles it.
// ---------------------------------------------------------------------------
__global__ void k_place(const int* __restrict__ ei) {
    int e = blockIdx.x * blockDim.x + threadIdx.x;
    if (e >= N_EDGES) return;
    int src = __ldg(&ei[e]);
    int dst = __ldg(&ei[N_EDGES + e]);
    if (((unsigned)src >= N_NODES) | ((unsigned)dst >= N_NODES)) return;
    int pos = atomicAdd(&g_cnt[dst], 1);
    if (pos < CAP) g_srcs[dst * CAP + pos] = src;
}

// ---------------------------------------------------------------------------
// Kernel 3 (k_agg): h[n] = x[n] + sum of neighbor rows. One warp per node;
// the ONLY writer of g_h (init copy eliminated). Overflow belt: if deg > CAP
// (P ~ 1e-30), the warp rescans the full edge list for dst==n.
// ---------------------------------------------------------------------------
__global__ void k_agg(const float* __restrict__ x, const int* __restrict__ ei) {
    int n    = (blockIdx.x * blockDim.x + threadIdx.x) >> 5;
    int lane = threadIdx.x & 31;
    if (n >= N_NODES) return;
    int cnt = g_cnt[n];
    float4 acc = __ldg((const float4*)(x + (size_t)n * D) + lane);

    if (cnt <= CAP) {
        const int* s = g_srcs + n * CAP;
        int j = 0;
        for (; j + 2 <= cnt; j += 2) {            // 2-deep pipeline
            int s0 = __ldg(&s[j]);
            int s1 = __ldg(&s[j + 1]);
            float4 v0 = __ldg((const float4*)(x + (size_t)s0 * D) + lane);
            float4 v1 = __ldg((const float4*)(x + (size_t)s1 * D) + lane);
            acc.x += v0.x + v1.x; acc.y += v0.y + v1.y;
            acc.z += v0.z + v1.z; acc.w += v0.w + v1.w;
        }
        if (j < cnt) {
            int s0 = __ldg(&s[j]);
            float4 v0 = __ldg((const float4*)(x + (size_t)s0 * D) + lane);
            acc.x += v0.x; acc.y += v0.y; acc.z += v0.z; acc.w += v0.w;
        }
    } else {
        // rare path: full scan (correctness belt; never executes for λ=12)
        for (int e = 0; e < N_EDGES; e++) {
            if (__ldg(&ei[N_EDGES + e]) == n) {
                int s0 = __ldg(&ei[e]);
                if ((unsigned)s0 < N_NODES) {
                    float4 v0 = __ldg((const float4*)(x + (size_t)s0 * D) + lane);
                    acc.x += v0.x; acc.y += v0.y; acc.z += v0.z; acc.w += v0.w;
                }
            }
        }
    }
    *(float4*)(g_h + (size_t)n * D + lane * 4) = acc;
}

// ---------------------------------------------------------------------------
// Kernel 4: h1 = relu(h @ W1 + b1), fused per-feature sum / sumsq partials.
// Tile: 64 rows x 128 cols per block, 256 threads, 8x4 outputs per thread.
// Inner loop uses explicit LDS.128 for the B fragment.
// ---------------------------------------------------------------------------
__global__ void k_gemm1(const float* __restrict__ W1,
                        const float* __restrict__ b1) {
    __shared__ float As[32][65];      // (k+m)%32 banks: conflict-free stores
    __shared__ __align__(16) float Bs[32][128];
    __shared__ float s_sum[128];
    __shared__ float s_sq [128];

    int t  = threadIdx.x;
    int tx = t & 31;                  // N-group: cols tx*4 .. tx*4+3
    int ty = t >> 5;                  // M-group: rows ty*8 .. ty*8+7
    int rowBase = blockIdx.x * 64;

    float acc[8][4];
    #pragma unroll
    for (int i = 0; i < 8; i++)
        #pragma unroll
        for (int j = 0; j < 4; j++) acc[i][j] = 0.f;

    for (int kc = 0; kc < D; kc += 32) {
        #pragma unroll
        for (int i = 0; i < 8; i++) {
            int idx = t + i * 256;            // 0..2047
            int k = idx & 31, m = idx >> 5;
            int row = rowBase + m;
            As[k][m] = (row < N_NODES) ? g_h[row * D + kc + k] : 0.f;
        }
        #pragma unroll
        for (int i = 0; i < 16; i++) {
            int idx = t + i * 256;            // 0..4095
            int n = idx & 127, k = idx >> 7;
            Bs[k][n] = W1[(kc + k) * D + n];
        }
        __syncthreads();

        #pragma unroll
        for (int k = 0; k < 32; k++) {
            float4 bv = *(const float4*)&Bs[k][tx * 4];   // LDS.128
            #pragma unroll
            for (int i = 0; i < 8; i++) {
                float a = As[k][ty * 8 + i];              // warp-broadcast
                acc[i][0] += a * bv.x;
                acc[i][1] += a * bv.y;
                acc[i][2] += a * bv.z;
                acc[i][3] += a * bv.w;
            }
        }
        __syncthreads();
    }

    if (t < 128) { s_sum[t] = 0.f; s_sq[t] = 0.f; }
    __syncthreads();

    float4 bb = *(const float4*)(b1 + tx * 4);
    float psum[4] = {0.f, 0.f, 0.f, 0.f};
    float psq [4] = {0.f, 0.f, 0.f, 0.f};

    #pragma unroll
    for (int i = 0; i < 8; i++) {
        int row = rowBase + ty * 8 + i;
        if (row < N_NODES) {
            float4 hv;
            hv.x = fmaxf(acc[i][0] + bb.x, 0.f);
            hv.y = fmaxf(acc[i][1] + bb.y, 0.f);
            hv.z = fmaxf(acc[i][2] + bb.z, 0.f);
            hv.w = fmaxf(acc[i][3] + bb.w, 0.f);
            *(float4*)(g_h1 + (size_t)row * D + tx * 4) = hv;
            psum[0] += hv.x; psq[0] += hv.x * hv.x;
            psum[1] += hv.y; psq[1] += hv.y * hv.y;
            psum[2] += hv.z; psq[2] += hv.z * hv.z;
            psum[3] += hv.w; psq[3] += hv.w * hv.w;
        }
    }
    #pragma unroll
    for (int j = 0; j < 4; j++) {
        atomicAdd(&s_sum[tx * 4 + j], psum[j]);
        atomicAdd(&s_sq [tx * 4 + j], psq [j]);
    }
    __syncthreads();
    if (t < 128) {
        atomicAdd(&g_sum[t], s_sum[t]);
        atomicAdd(&g_sq [t], s_sq [t]);
    }
}

// ---------------------------------------------------------------------------
// Kernel 5 (1 block, 128 threads): finalize BN stats, fold into Weff/ceff.
//   g_f     = rsqrt(var_f + eps) * gamma_f
//   Weff    = g_f * W2l[f,c]
//   ceff[c] = bl[c] + sum_f [ (beta_f - mean_f*g_f)*W2l[f,c] + b2[f]*Wl[f,c] ]
// ---------------------------------------------------------------------------
__global__ void k_stats(const float* __restrict__ b2, const float* __restrict__ Wl,
                        const float* __restrict__ bl,
                        const float* __restrict__ gamma, const float* __restrict__ beta) {
    int f = threadIdx.x;   // 0..127
    float mean = g_sum[f] * (1.0f / N_NODES);
    float var  = g_sq [f] * (1.0f / N_NODES) - mean * mean;
    float g    = rsqrtf(var + BN_EPS) * gamma[f];

    float w2l0 = g_W2l[f * 2 + 0];
    float w2l1 = g_W2l[f * 2 + 1];
    g_Weff[f * 2 + 0] = g * w2l0;
    g_Weff[f * 2 + 1] = g * w2l1;

    float bias = beta[f] - mean * g;
    float p0 = bias * w2l0 + b2[f] * Wl[f * 2 + 0];
    float p1 = bias * w2l1 + b2[f] * Wl[f * 2 + 1];

    __shared__ float r0[128], r1[128];
    r0[f] = p0; r1[f] = p1;
    __syncthreads();
    for (int s = 64; s > 0; s >>= 1) {
        if (f < s) { r0[f] += r0[f + s]; r1[f] += r1[f + s]; }
        __syncthreads();
    }
    if (f == 0) {
        g_ceff[0] = r0[0] + bl[0];
        g_ceff[1] = r1[0] + bl[1];
    }
}

// ---------------------------------------------------------------------------
// Kernel 6: out[n,c] = dot(h1[n,:], Weff[:,c]) + ceff[c]. One warp per node.
// ---------------------------------------------------------------------------
__global__ void k_out(float* __restrict__ out) {
    __shared__ float w[256];
    __shared__ float c0s, c1s;
    int t = threadIdx.x;
    w[t] = g_Weff[t];
    if (t == 0) { c0s = g_ceff[0]; c1s = g_ceff[1]; }
    __syncthreads();

    int lane = t & 31;
    int n = (blockIdx.x * blockDim.x + t) >> 5;     // one node per warp
    if (n >= N_NODES) return;

    float4 h = *(const float4*)(g_h1 + (size_t)n * D + lane * 4);
    int b = lane * 8;  // f = lane*4+q -> w[(lane*4+q)*2 + c]
    float s0 = h.x * w[b + 0] + h.y * w[b + 2] + h.z * w[b + 4] + h.w * w[b + 6];
    float s1 = h.x * w[b + 1] + h.y * w[b + 3] + h.z * w[b + 5] + h.w * w[b + 7];
    #pragma unroll
    for (int o = 16; o > 0; o >>= 1) {
        s0 += __shfl_down_sync(0xFFFFFFFFu, s0, o);
        s1 += __shfl_down_sync(0xFFFFFFFFu, s1, o);
    }
    if (lane == 0) {
        out[n * 2 + 0] = s0 + c0s;
        out[n * 2 + 1] = s1 + c1s;
    }
}

// ---------------------------------------------------------------------------
extern "C" void kernel_launch(void* const* d_in, const int* in_sizes, int n_in,
                              void* d_out, int out_size) {
    const float* x     = (const float*)d_in[0];
    const int*   ei    = (const int*)  d_in[1];   // int32 (JAX x64-disabled)
    const float* W1    = (const float*)d_in[2];
    const float* b1    = (const float*)d_in[3];
    const float* gamma = (const float*)d_in[4];
    const float* beta  = (const float*)d_in[5];
    const float* W2    = (const float*)d_in[6];
    const float* b2    = (const float*)d_in[7];
    const float* Wl    = (const float*)d_in[8];
    const float* bl    = (const float*)d_in[9];
    float*       out   = (float*)      d_out;

    // 1) zero counters/stats + W2l = W2@Wl (one merged launch)
    k_pre<<<NB_CNT + 17, 256>>>(W2, Wl);
    // 2) bucket edges by dst (one thread per edge)
    k_place<<<(N_EDGES + 255) / 256, 256>>>(ei);
    // 3) h = x + aggregate (one warp per node; sole writer of g_h)
    k_agg<<<(N_NODES * 32 + 255) / 256, 256>>>(x, ei);
    // 4) h1 = relu(h@W1+b1) + BN stat partials
    k_gemm1<<<(N_NODES + 63) / 64, 256>>>(W1, b1);
    // 5) finalize BN + fold into Weff[128x2], ceff[2]
    k_stats<<<1, 128>>>(b2, Wl, bl, gamma, beta);
    // 6) out = h1 @ Weff + ceff
    k_out<<<(N_NODES * 32 + 255) / 256, 256>>>(out);
}